// round 13
// baseline (speedup 1.0000x reference)
#include <cuda_runtime.h>
#include <cuda_bf16.h>

// PatchFFTLoss round 13: R8 scalar math + R9 scale-fold + SMEM state stash.
//  - thread pair (t) = (input,target) of one patch; real-input 8x8 FFT,
//    Hermitian in v; canonical bins; pair-diff epilogue via xor-1 shuffles.
//  - X1/X2/X3 row-FFT outputs (48 floats) stashed in per-thread SMEM slots
//    ([row][tid] layout, conflict-free, no syncs) -> live reg state ~46
//    -> 9 CTAs/SM (56-reg budget) -> 36 warps/SM vs 24 before.
//  - per-row streaming loads; latency hidden by warp count.
//  - static grid, fused last-block-done reduction, bit-deterministic.

#define NPATCH   (16 * 3 * 64 * 64)       // 196608
#define NTHREADS (NPATCH * 2)             // 393216
#define BLOCK    128
#define NBLOCKS  (NTHREADS / BLOCK)       // 3072
#define LN2      0.69314718055994530942f
#define FINAL_SCALE ((LN2 * LN2) / (2.0f * 12582912.0f))
#define FULLM    0xffffffffu

__device__ float g_partials[NBLOCKS];
__device__ unsigned int g_count = 0;

// g on unnormalized FFT value: sign(x) * log2(1 + |x|/8)
__device__ __forceinline__ float gfun(float x) {
    return copysignf(__log2f(fmaf(0.125f, fabsf(x), 1.0f)), x);
}

// d^2 of g across the (input,target) lane pair (xor 1)
__device__ __forceinline__ float ddq(float x) {
    float gv = gfun(x);
    float d = gv - __shfl_xor_sync(FULLM, gv, 1);
    return d * d;
}

// scalar complex 8-pt FFT in place, natural-order bins (validated r2-r12)
__device__ __forceinline__ void fft8c(float* xr, float* xi)
{
    const float C = 0.70710678118654752440f;
    float A0r=xr[0]+xr[4], A0i=xi[0]+xi[4];
    float A1r=xr[1]+xr[5], A1i=xi[1]+xi[5];
    float A2r=xr[2]+xr[6], A2i=xi[2]+xi[6];
    float A3r=xr[3]+xr[7], A3i=xi[3]+xi[7];
    float B0r=xr[0]-xr[4], B0i=xi[0]-xi[4];
    float d1r=xr[1]-xr[5], d1i=xi[1]-xi[5];
    float B1r=C*(d1r+d1i), B1i=C*(d1i-d1r);
    float B2r=xi[2]-xi[6], B2i=xr[6]-xr[2];
    float d3r=xr[3]-xr[7], d3i=xi[3]-xi[7];
    float B3r=C*(d3i-d3r), B3i=-C*(d3r+d3i);

    float A20r=A0r+A2r, A20i=A0i+A2i;
    float A22r=A0r-A2r, A22i=A0i-A2i;
    float A21r=A1r+A3r, A21i=A1i+A3i;
    float A23r=A1i-A3i, A23i=A3r-A1r;
    float B20r=B0r+B2r, B20i=B0i+B2i;
    float B22r=B0r-B2r, B22i=B0i-B2i;
    float B21r=B1r+B3r, B21i=B1i+B3i;
    float B23r=B1i-B3i, B23i=B3r-B1r;

    xr[0]=A20r+A21r; xi[0]=A20i+A21i;
    xr[4]=A20r-A21r; xi[4]=A20i-A21i;
    xr[2]=A22r+A23r; xi[2]=A22i+A23i;
    xr[6]=A22r-A23r; xi[6]=A22i-A23i;
    xr[1]=B20r+B21r; xi[1]=B20i+B21i;
    xr[5]=B20r-B21r; xi[5]=B20i-B21i;
    xr[3]=B22r+B23r; xi[3]=B22i+B23i;
    xr[7]=B22r-B23r; xi[7]=B22i-B23i;
}

__global__ void __launch_bounds__(BLOCK, 9)
patch_fft_loss_kernel(const float* __restrict__ inp,
                      const float* __restrict__ tgt,
                      float* __restrict__ out)
{
    // per-thread SMEM stash: X1 (float2) and X2+X3 (float4) per row
    __shared__ float2 sX1[8][BLOCK];      // 8 KB
    __shared__ float4 sX23[8][BLOCK];     // 16 KB
    __shared__ float  smw[BLOCK / 32];
    __shared__ bool   isLast;

    const int tid = threadIdx.x;
    const int gid = blockIdx.x * BLOCK + tid;
    const int t  = gid & 1;           // 0 = input, 1 = target
    const int p  = gid >> 1;          // patch index
    const int pw = p & 63;
    const int ph = (p >> 6) & 63;
    const int bc = p >> 12;
    const float* __restrict__ src = t ? tgt : inp;
    const size_t base = ((size_t)(bc * 512 + ph * 8)) * 512 + (size_t)pw * 8;

    const float C = 0.70710678118654752440f;

    // ---- phase A: per-row load + real row FFT; stash X1/X2/X3 to SMEM ----
    float R0[8], R4[8];
    #pragma unroll
    for (int r = 0; r < 8; r++) {
        const float* rp = src + base + (size_t)r * 512;
        float4 a = *(const float4*)(rp);
        float4 b = *(const float4*)(rp + 4);
        float a04p=a.x+b.x, a04m=a.x-b.x;
        float a26p=a.z+b.z, a26m=a.z-b.z;
        float E0=a04p+a26p, E2=a04p-a26p;
        float b15p=a.y+b.y, b15m=a.y-b.y;
        float b37p=a.w+b.w, b37m=a.w-b.w;
        float O0=b15p+b37p, O2=b15p-b37p;
        float t1 =  C*(b15m-b37m);
        float t2 = -C*(b15m+b37m);
        R0[r] = E0 + O0;
        R4[r] = E0 - O0;
        sX1[r][tid]  = make_float2(a04m + t1, -a26m + t2);
        sX23[r][tid] = make_float4(E2, -O2, a04m - t1, a26m + t2);
    }

    float acc1 = 0.0f, acc2 = 0.0f;

    // ---- real columns v = 0 and v = 4: bins u = 0..4 ----
    #pragma unroll
    for (int k = 0; k < 2; k++) {
        const float* c = k ? R4 : R0;
        float a04p=c[0]+c[4], a04m=c[0]-c[4];
        float a26p=c[2]+c[6], a26m=c[2]-c[6];
        float E0=a04p+a26p, E2=a04p-a26p;
        float b15p=c[1]+c[5], b15m=c[1]-c[5];
        float b37p=c[3]+c[7], b37m=c[3]-c[7];
        float O0=b15p+b37p, O2=b15p-b37p;
        float t1 =  C*(b15m-b37m);
        float t2 = -C*(b15m+b37m);
        // u=0,4 self-conjugate (imag exactly 0): weight 1
        acc1 += ddq(E0 + O0);
        acc1 += ddq(E0 - O0);
        // u=1..3: weight 2
        acc2 += ddq(a04m + t1) + ddq(-a26m + t2);
        acc2 += ddq(E2)        + ddq(-O2);
        acc2 += ddq(a04m - t1) + ddq( a26m + t2);
    }

    // ---- column v = 1 from SMEM stash ----
    {
        float xr[8], xi[8];
        #pragma unroll
        for (int r = 0; r < 8; r++) {
            float2 v = sX1[r][tid];
            xr[r] = v.x; xi[r] = v.y;
        }
        fft8c(xr, xi);
        #pragma unroll
        for (int u = 0; u < 8; u++) acc2 += ddq(xr[u]) + ddq(xi[u]);
    }

    // ---- columns v = 2 and v = 3 from SMEM stash ----
    {
        float x2r[8], x2i[8], x3r[8], x3i[8];
        #pragma unroll
        for (int r = 0; r < 8; r++) {
            float4 v = sX23[r][tid];
            x2r[r] = v.x; x2i[r] = v.y; x3r[r] = v.z; x3i[r] = v.w;
        }
        fft8c(x2r, x2i);
        #pragma unroll
        for (int u = 0; u < 8; u++) acc2 += ddq(x2r[u]) + ddq(x2i[u]);
        fft8c(x3r, x3i);
        #pragma unroll
        for (int u = 0; u < 8; u++) acc2 += ddq(x3r[u]) + ddq(x3i[u]);
    }

    float acc = fmaf(2.0f, acc2, acc1);

    // ---- deterministic reduction: warp -> block -> last-block-done global ----
    #pragma unroll
    for (int o = 16; o > 0; o >>= 1)
        acc += __shfl_xor_sync(FULLM, acc, o);

    if ((tid & 31) == 0) smw[tid >> 5] = acc;
    __syncthreads();
    if (tid == 0) {
        float s = 0.0f;
        #pragma unroll
        for (int i = 0; i < BLOCK / 32; i++) s += smw[i];
        g_partials[blockIdx.x] = s;
        __threadfence();
        unsigned old = atomicInc(&g_count, NBLOCKS - 1);  // wraps to 0 on last
        isLast = (old == NBLOCKS - 1);
    }
    __syncthreads();

    if (isLast) {
        float a = 0.0f;
        #pragma unroll
        for (int i = 0; i < NBLOCKS / BLOCK; i++)
            a += __ldcg(&g_partials[tid + i * BLOCK]);
        #pragma unroll
        for (int o = 16; o > 0; o >>= 1)
            a += __shfl_xor_sync(FULLM, a, o);
        if ((tid & 31) == 0) smw[tid >> 5] = a;
        __syncthreads();
        if (tid == 0) {
            float s = 0.0f;
            #pragma unroll
            for (int i = 0; i < BLOCK / 32; i++) s += smw[i];
            out[0] = s * FINAL_SCALE;
        }
    }
}

extern "C" void kernel_launch(void* const* d_in, const int* in_sizes, int n_in,
                              void* d_out, int out_size)
{
    const float* inp = (const float*)d_in[0];
    const float* tgt = (const float*)d_in[1];
    patch_fft_loss_kernel<<<NBLOCKS, BLOCK>>>(inp, tgt, (float*)d_out);
}

// round 14
// speedup vs baseline: 1.8763x; 1.8763x over previous
#include <cuda_runtime.h>
#include <cuda_bf16.h>

// PatchFFTLoss round 14: R8 exactly (the proven local optimum: thread pair =
// (input,target) of one patch, pure-scalar real-input 8x8 FFT, Hermitian in
// v, 80 regs / 6 CTAs/SM, front-batched loads, shuffles only in the 64-bin
// epilogue) + R9's scale-fold as the single delta:
//   g(x) = copysign(log2(fma(1/8, |x|, 1)), x) on the UNNORMALIZED FFT
// removes all 64 per-thread input-normalization FMULs. No f32x2 packing
// (R9 showed its pack MOVs increase total issue), no persistent CTAs (R10),
// no extra lane splitting (R11), no multi-patch pipeline (R12), no SMEM
// stash (R13) — each regressed with a diagnosed mechanism.

#define NPATCH   (16 * 3 * 64 * 64)       // 196608
#define NTHREADS (NPATCH * 2)             // 393216
#define BLOCK    128
#define NBLOCKS  (NTHREADS / BLOCK)       // 3072
#define LN2      0.69314718055994530942f
#define FINAL_SCALE ((LN2 * LN2) / (2.0f * 12582912.0f))
#define FULLM    0xffffffffu

__device__ float g_partials[NBLOCKS];
__device__ unsigned int g_count = 0;

// g on unnormalized FFT value: sign(x) * log2(1 + |x|/8)
__device__ __forceinline__ float gfun(float x) {
    return copysignf(__log2f(fmaf(0.125f, fabsf(x), 1.0f)), x);
}

// d^2 of g across the (input,target) lane pair (xor 1)
__device__ __forceinline__ float ddq(float x) {
    float gv = gfun(x);
    float d = gv - __shfl_xor_sync(FULLM, gv, 1);
    return d * d;
}

// scalar complex 8-pt FFT in place, natural-order bins (validated r2-r13)
__device__ __forceinline__ void fft8c(float* xr, float* xi)
{
    const float C = 0.70710678118654752440f;
    float A0r=xr[0]+xr[4], A0i=xi[0]+xi[4];
    float A1r=xr[1]+xr[5], A1i=xi[1]+xi[5];
    float A2r=xr[2]+xr[6], A2i=xi[2]+xi[6];
    float A3r=xr[3]+xr[7], A3i=xi[3]+xi[7];
    float B0r=xr[0]-xr[4], B0i=xi[0]-xi[4];
    float d1r=xr[1]-xr[5], d1i=xi[1]-xi[5];
    float B1r=C*(d1r+d1i), B1i=C*(d1i-d1r);
    float B2r=xi[2]-xi[6], B2i=xr[6]-xr[2];
    float d3r=xr[3]-xr[7], d3i=xi[3]-xi[7];
    float B3r=C*(d3i-d3r), B3i=-C*(d3r+d3i);

    float A20r=A0r+A2r, A20i=A0i+A2i;
    float A22r=A0r-A2r, A22i=A0i-A2i;
    float A21r=A1r+A3r, A21i=A1i+A3i;
    float A23r=A1i-A3i, A23i=A3r-A1r;
    float B20r=B0r+B2r, B20i=B0i+B2i;
    float B22r=B0r-B2r, B22i=B0i-B2i;
    float B21r=B1r+B3r, B21i=B1i+B3i;
    float B23r=B1i-B3i, B23i=B3r-B1r;

    xr[0]=A20r+A21r; xi[0]=A20i+A21i;
    xr[4]=A20r-A21r; xi[4]=A20i-A21i;
    xr[2]=A22r+A23r; xi[2]=A22i+A23i;
    xr[6]=A22r-A23r; xi[6]=A22i-A23i;
    xr[1]=B20r+B21r; xi[1]=B20i+B21i;
    xr[5]=B20r-B21r; xi[5]=B20i-B21i;
    xr[3]=B22r+B23r; xi[3]=B22i+B23i;
    xr[7]=B22r-B23r; xi[7]=B22i-B23i;
}

__global__ void __launch_bounds__(BLOCK, 6)
patch_fft_loss_kernel(const float* __restrict__ inp,
                      const float* __restrict__ tgt,
                      float* __restrict__ out)
{
    const int gid = blockIdx.x * BLOCK + threadIdx.x;
    const int t  = gid & 1;           // 0 = input, 1 = target
    const int p  = gid >> 1;          // patch index
    const int pw = p & 63;
    const int ph = (p >> 6) & 63;
    const int bc = p >> 12;
    const float* __restrict__ src = t ? tgt : inp;
    const size_t base = ((size_t)(bc * 512 + ph * 8)) * 512 + (size_t)pw * 8;

    const float C = 0.70710678118654752440f;

    // ---- front-batched loads: 16 LDG.128 ----
    float4 la[8], lb[8];
    #pragma unroll
    for (int r = 0; r < 8; r++) {
        const float* rp = src + base + (size_t)r * 512;
        la[r] = *(const float4*)(rp);
        lb[r] = *(const float4*)(rp + 4);
    }

    // ---- real row FFTs (unnormalized), keep v = 0..4 (v0, v4 real) ----
    float R0[8], R4[8];
    float X1r[8], X1i[8], X2r[8], X2i[8], X3r[8], X3i[8];
    #pragma unroll
    for (int r = 0; r < 8; r++) {
        float x0=la[r].x, x1=la[r].y, x2=la[r].z, x3=la[r].w;
        float x4=lb[r].x, x5=lb[r].y, x6=lb[r].z, x7=lb[r].w;
        float a04p=x0+x4, a04m=x0-x4;
        float a26p=x2+x6, a26m=x2-x6;
        float E0=a04p+a26p, E2=a04p-a26p;
        float b15p=x1+x5, b15m=x1-x5;
        float b37p=x3+x7, b37m=x3-x7;
        float O0=b15p+b37p, O2=b15p-b37p;
        float t1 =  C*(b15m-b37m);
        float t2 = -C*(b15m+b37m);
        R0[r]  = E0 + O0;
        R4[r]  = E0 - O0;
        X1r[r] = a04m + t1;  X1i[r] = -a26m + t2;
        X2r[r] = E2;         X2i[r] = -O2;
        X3r[r] = a04m - t1;  X3i[r] =  a26m + t2;
    }

    float acc1 = 0.0f, acc2 = 0.0f;

    // ---- columns v = 0 and v = 4: real FFT, bins u = 0..4 ----
    #pragma unroll
    for (int k = 0; k < 2; k++) {
        const float* c = k ? R4 : R0;
        float a04p=c[0]+c[4], a04m=c[0]-c[4];
        float a26p=c[2]+c[6], a26m=c[2]-c[6];
        float E0=a04p+a26p, E2=a04p-a26p;
        float b15p=c[1]+c[5], b15m=c[1]-c[5];
        float b37p=c[3]+c[7], b37m=c[3]-c[7];
        float O0=b15p+b37p, O2=b15p-b37p;
        float t1 =  C*(b15m-b37m);
        float t2 = -C*(b15m+b37m);
        // u=0,4 self-conjugate (imag exactly 0): weight 1
        acc1 += ddq(E0 + O0);
        acc1 += ddq(E0 - O0);
        // u=1..3: weight 2
        acc2 += ddq(a04m + t1) + ddq(-a26m + t2);
        acc2 += ddq(E2)        + ddq(-O2);
        acc2 += ddq(a04m - t1) + ddq( a26m + t2);
    }

    // ---- columns v = 1..3: complex FFT, all u, weight 2 ----
    fft8c(X1r, X1i);
    #pragma unroll
    for (int u = 0; u < 8; u++) acc2 += ddq(X1r[u]) + ddq(X1i[u]);
    fft8c(X2r, X2i);
    #pragma unroll
    for (int u = 0; u < 8; u++) acc2 += ddq(X2r[u]) + ddq(X2i[u]);
    fft8c(X3r, X3i);
    #pragma unroll
    for (int u = 0; u < 8; u++) acc2 += ddq(X3r[u]) + ddq(X3i[u]);

    float acc = fmaf(2.0f, acc2, acc1);

    // ---- deterministic reduction: warp -> block -> last-block-done global ----
    #pragma unroll
    for (int o = 16; o > 0; o >>= 1)
        acc += __shfl_xor_sync(FULLM, acc, o);

    __shared__ float smw[BLOCK / 32];
    __shared__ bool isLast;
    if ((threadIdx.x & 31) == 0) smw[threadIdx.x >> 5] = acc;
    __syncthreads();
    if (threadIdx.x == 0) {
        float s = 0.0f;
        #pragma unroll
        for (int i = 0; i < BLOCK / 32; i++) s += smw[i];
        g_partials[blockIdx.x] = s;
        __threadfence();
        unsigned old = atomicInc(&g_count, NBLOCKS - 1);  // wraps to 0 on last
        isLast = (old == NBLOCKS - 1);
    }
    __syncthreads();

    if (isLast) {
        float a = 0.0f;
        #pragma unroll
        for (int i = 0; i < NBLOCKS / BLOCK; i++)
            a += __ldcg(&g_partials[threadIdx.x + i * BLOCK]);
        #pragma unroll
        for (int o = 16; o > 0; o >>= 1)
            a += __shfl_xor_sync(FULLM, a, o);
        if ((threadIdx.x & 31) == 0) smw[threadIdx.x >> 5] = a;
        __syncthreads();
        if (threadIdx.x == 0) {
            float s = 0.0f;
            #pragma unroll
            for (int i = 0; i < BLOCK / 32; i++) s += smw[i];
            out[0] = s * FINAL_SCALE;
        }
    }
}

extern "C" void kernel_launch(void* const* d_in, const int* in_sizes, int n_in,
                              void* d_out, int out_size)
{
    const float* inp = (const float*)d_in[0];
    const float* tgt = (const float*)d_in[1];
    patch_fft_loss_kernel<<<NBLOCKS, BLOCK>>>(inp, tgt, (float*)d_out);
}